// round 13
// baseline (speedup 1.0000x reference)
#include <cuda_runtime.h>

#define IN_F   128
#define OUT_F  128
#define MAX_NODES 10000
#define MAX_EDGES 640000
#define TILE_N 32
#define KK     256     // fused K dimension: [agg_norm | x]
#define KC     32      // K-chunk size for combine
#define PREP_T 256
#define PREP_EPT 8     // covers E for any grid >= 80K threads

// Scratch (no device allocations allowed). Zero-initialized at load;
// g_cnt is reset inside prep's scan phase each call -> deterministic state.
__device__ float4   g_agg4[MAX_NODES * (IN_F / 4)];
__device__ int      g_cnt[MAX_NODES];
__device__ int      g_off[MAX_NODES + 1];
__device__ int      g_srcl[MAX_EDGES];
__device__ int      g_kmax;                 // 128 if B==0, else 256
__device__ unsigned g_bar_count;            // grid-barrier state (self-resetting)
__device__ unsigned g_bar_gen;

// Software grid barrier (all blocks co-resident by construction).
__device__ __forceinline__ void grid_barrier(int nblocks) {
    __syncthreads();
    if (threadIdx.x == 0) {
        volatile unsigned* vgen = &g_bar_gen;
        unsigned gen = *vgen;
        __threadfence();
        if (atomicAdd(&g_bar_count, 1u) == (unsigned)(nblocks - 1)) {
            g_bar_count = 0;
            __threadfence();
            atomicAdd(&g_bar_gen, 1u);
        } else {
            while (*vgen == gen) { __nanosleep(64); }
        }
        __threadfence();
    }
    __syncthreads();
}

__device__ __forceinline__ int detect_is64(const unsigned int* __restrict__ ei_w,
                                           int E, int* s_flag) {
    if (threadIdx.x < 32) {
        unsigned int v = ((int)threadIdx.x < E) ? ei_w[2 * threadIdx.x + 1] : 0u;
        unsigned int any = __ballot_sync(0xffffffffu, v != 0u);
        if (threadIdx.x == 0) *s_flag = (any == 0u) ? 1 : 0;
    }
    __syncthreads();
    return *s_flag;
}

__device__ __forceinline__ int load_idx_d(const void* __restrict__ ei,
                                          long long pos, int is64) {
    if (is64) return (int)((const long long*)ei)[pos];
    return ((const int*)ei)[pos];
}

// ---------------------------------------------------------------------------
// 1) PERSISTENT prep: deg histogram -> grid barrier -> scan (block 0) +
//    B-check (block 1) -> grid barrier -> CSR fill.
//    src/dst/rank live in registers across all three phases.
// ---------------------------------------------------------------------------
__global__ __launch_bounds__(PREP_T, 4)
void prep_kernel(const void* __restrict__ ei, const float4* __restrict__ B4,
                 int E, int n_nodes, int nblocks) {
    __shared__ int s_is64;
    __shared__ int wsum[8];
    int is64 = detect_is64((const unsigned int*)ei, E, &s_is64);

    int T = nblocks * PREP_T;
    int t0 = blockIdx.x * PREP_T + threadIdx.x;

    int src[PREP_EPT], dst[PREP_EPT], rnk[PREP_EPT];
#pragma unroll
    for (int i = 0; i < PREP_EPT; i++) {
        int e = t0 + i * T;
        if (e < E) {
            src[i] = min(max(load_idx_d(ei, e, is64), 0), n_nodes - 1);
            dst[i] = min(max(load_idx_d(ei, (long long)E + e, is64), 0), n_nodes - 1);
        } else { src[i] = -1; dst[i] = 0; }
    }
#pragma unroll
    for (int i = 0; i < PREP_EPT; i++)
        rnk[i] = (src[i] >= 0) ? atomicAdd(&g_cnt[dst[i]], 1) : 0;

    grid_barrier(nblocks);

    if (blockIdx.x == 0) {
        // 256-thread exclusive scan, PER=40 (256*40=10240 >= n_nodes).
        // Two passes over g_cnt (L1-hot) to avoid a 40-register array;
        // also resets g_cnt for the next invocation.
        const int PER = 40;
        int t = threadIdx.x, lane = t & 31, wid = t >> 5;
        int base = t * PER;
        int s = 0;
        for (int i = 0; i < PER; i++) {
            int idx = base + i;
            if (idx < n_nodes) s += g_cnt[idx];
        }
        int v = s;
#pragma unroll
        for (int o = 1; o < 32; o <<= 1) {
            int u = __shfl_up_sync(0xffffffffu, v, o);
            if (lane >= o) v += u;
        }
        if (lane == 31) wsum[wid] = v;
        __syncthreads();
        if (wid == 0 && lane < 8) {
            int w = wsum[lane];
#pragma unroll
            for (int o = 1; o < 8; o <<= 1) {
                int u = __shfl_up_sync(0xffu, w, o);
                if (lane >= o) w += u;
            }
            wsum[lane] = w;
        }
        __syncthreads();
        int wbase = (wid == 0) ? 0 : wsum[wid - 1];
        int run = wbase + (v - s);          // exclusive base for this thread
        for (int i = 0; i < PER; i++) {
            int idx = base + i;
            if (idx < n_nodes) {
                g_off[idx] = run;
                int c = g_cnt[idx];
                g_cnt[idx] = 0;             // reset for next call
                run += c;
            }
        }
        if (t == 255) g_off[n_nodes] = wsum[7];
    } else if (blockIdx.x == 1) {
        // B == 0 check (64 KB), OR-reduced across block 1
        int nz = 0;
        for (int i = threadIdx.x; i < (OUT_F * IN_F) / 4; i += PREP_T) {
            float4 b = B4[i];
            if (b.x != 0.f || b.y != 0.f || b.z != 0.f || b.w != 0.f) nz = 1;
        }
        int bnz = __syncthreads_or(nz);
        if (threadIdx.x == 0) g_kmax = bnz ? KK : IN_F;
    }

    grid_barrier(nblocks);

#pragma unroll
    for (int i = 0; i < PREP_EPT; i++) {
        if (src[i] >= 0) {
            int pos = g_off[dst[i]] + rnk[i];
            if (pos >= 0 && pos < MAX_EDGES) g_srcl[pos] = src[i];
        }
    }
}

// ---------------------------------------------------------------------------
// 2) gather: one warp per node (proven L2-roofline form, 1250 blocks).
// ---------------------------------------------------------------------------
__global__ __launch_bounds__(256)
void gather_kernel(const float* __restrict__ x, int n_nodes) {
    int warp = (int)((blockIdx.x * (long long)blockDim.x + threadIdx.x) >> 5);
    int lane = threadIdx.x & 31;
    if (warp >= n_nodes) return;

    int beg = g_off[warp];
    int end = g_off[warp + 1];
    const float4* x4 = (const float4*)x;

    float4 acc = make_float4(0.f, 0.f, 0.f, 0.f);
    int j = beg;
    for (; j + 8 <= end; j += 8) {
        int i0 = g_srcl[j + 0], i1 = g_srcl[j + 1];
        int i2 = g_srcl[j + 2], i3 = g_srcl[j + 3];
        int i4 = g_srcl[j + 4], i5 = g_srcl[j + 5];
        int i6 = g_srcl[j + 6], i7 = g_srcl[j + 7];
        float4 v0 = x4[(size_t)i0 * (IN_F / 4) + lane];
        float4 v1 = x4[(size_t)i1 * (IN_F / 4) + lane];
        float4 v2 = x4[(size_t)i2 * (IN_F / 4) + lane];
        float4 v3 = x4[(size_t)i3 * (IN_F / 4) + lane];
        float4 v4 = x4[(size_t)i4 * (IN_F / 4) + lane];
        float4 v5 = x4[(size_t)i5 * (IN_F / 4) + lane];
        float4 v6 = x4[(size_t)i6 * (IN_F / 4) + lane];
        float4 v7 = x4[(size_t)i7 * (IN_F / 4) + lane];
        acc.x += (v0.x + v1.x) + (v2.x + v3.x) + (v4.x + v5.x) + (v6.x + v7.x);
        acc.y += (v0.y + v1.y) + (v2.y + v3.y) + (v4.y + v5.y) + (v6.y + v7.y);
        acc.z += (v0.z + v1.z) + (v2.z + v3.z) + (v4.z + v5.z) + (v6.z + v7.z);
        acc.w += (v0.w + v1.w) + (v2.w + v3.w) + (v4.w + v5.w) + (v6.w + v7.w);
    }
    for (; j < end; j++) {
        int idx = g_srcl[j];
        float4 v = x4[(size_t)idx * (IN_F / 4) + lane];
        acc.x += v.x; acc.y += v.y; acc.z += v.z; acc.w += v.w;
    }
    int deg = end - beg;
    float inv = 1.0f / (float)((deg == 0) ? 1 : deg);
    acc.x *= inv; acc.y *= inv; acc.z *= inv; acc.w *= inv;
    g_agg4[(size_t)warp * (IN_F / 4) + lane] = acc;
}

// ---------------------------------------------------------------------------
// 3) combine (R9-proven): out = agg_norm @ W^T (+ x @ B.T iff B != 0).
//    Packed f32x2 FMA; A tile transposed so a node pair is one ld.shared.b64.
// ---------------------------------------------------------------------------
__global__ __launch_bounds__(256)
void combine_kernel(const float* __restrict__ x,
                    const float* __restrict__ W,
                    const float* __restrict__ B,
                    float* __restrict__ out, int n_nodes) {
    __shared__ float Wsh[KC][OUT_F + 4];      // [kk][o], row stride 132
    __shared__ float Ash[KC][TILE_N + 2];     // transposed [kk][node], stride 34

    int tid = threadIdx.x;
    int n0 = blockIdx.x * TILE_N;
    const float* agg = (const float*)g_agg4;
    int kmax = g_kmax;                        // uniform: 128 (B==0) or 256

    int og = tid & 31;   // outputs [og*4, og*4+3]
    int ng = tid >> 5;   // nodes   [ng*4, ng*4+3]

    unsigned long long acc[2][4];
#pragma unroll
    for (int p = 0; p < 2; p++)
#pragma unroll
        for (int o = 0; o < 4; o++) acc[p][o] = 0ull;

    for (int kc = 0; kc < kmax; kc += KC) {
        for (int i = tid; i < KC * OUT_F; i += 256) {
            int kk = i & (KC - 1);
            int o  = i >> 5;
            int kg = kc + kk;
            Wsh[kk][o] = (kg < IN_F) ? W[o * IN_F + kg]
                                     : B[o * IN_F + (kg - IN_F)];
        }
        for (int i = tid; i < TILE_N * KC; i += 256) {
            int nl = i >> 5;
            int kk = i & (KC - 1);
            int n  = n0 + nl;
            int kg = kc + kk;
            float v = 0.0f;
            if (n < n_nodes)
                v = (kg < IN_F) ? agg[n * IN_F + kg]
                                : x[n * IN_F + (kg - IN_F)];
            Ash[kk][nl] = v;
        }
        __syncthreads();

#pragma unroll
        for (int kk = 0; kk < KC; kk++) {
            float4 w = *(const float4*)&Wsh[kk][og * 4];
            unsigned long long wx, wy, wz, ww;
            asm("mov.b64 %0, {%1, %1};" : "=l"(wx) : "f"(w.x));
            asm("mov.b64 %0, {%1, %1};" : "=l"(wy) : "f"(w.y));
            asm("mov.b64 %0, {%1, %1};" : "=l"(wz) : "f"(w.z));
            asm("mov.b64 %0, {%1, %1};" : "=l"(ww) : "f"(w.w));
#pragma unroll
            for (int p = 0; p < 2; p++) {
                unsigned long long a2 =
                    *(const unsigned long long*)&Ash[kk][ng * 4 + p * 2];
                asm("fma.rn.f32x2 %0, %1, %2, %0;" : "+l"(acc[p][0]) : "l"(wx), "l"(a2));
                asm("fma.rn.f32x2 %0, %1, %2, %0;" : "+l"(acc[p][1]) : "l"(wy), "l"(a2));
                asm("fma.rn.f32x2 %0, %1, %2, %0;" : "+l"(acc[p][2]) : "l"(wz), "l"(a2));
                asm("fma.rn.f32x2 %0, %1, %2, %0;" : "+l"(acc[p][3]) : "l"(ww), "l"(a2));
            }
        }
        __syncthreads();
    }

#pragma unroll
    for (int p = 0; p < 2; p++) {
        float4 r0, r1;
        asm("mov.b64 {%0, %1}, %2;" : "=f"(r0.x), "=f"(r1.x) : "l"(acc[p][0]));
        asm("mov.b64 {%0, %1}, %2;" : "=f"(r0.y), "=f"(r1.y) : "l"(acc[p][1]));
        asm("mov.b64 {%0, %1}, %2;" : "=f"(r0.z), "=f"(r1.z) : "l"(acc[p][2]));
        asm("mov.b64 {%0, %1}, %2;" : "=f"(r0.w), "=f"(r1.w) : "l"(acc[p][3]));
        int na = n0 + ng * 4 + p * 2;
        int nb = na + 1;
        if (na < n_nodes) *(float4*)(out + (size_t)na * OUT_F + og * 4) = r0;
        if (nb < n_nodes) *(float4*)(out + (size_t)nb * OUT_F + og * 4) = r1;
    }
}

// ---------------------------------------------------------------------------
// kernel_launch
// Inputs: x [10000,128] f32, edge_index [2,640000] (int32 OR int64 — detected
// at runtime), W [128,128] f32, B [128,128] f32. Output: [10000,128] f32.
// ---------------------------------------------------------------------------
extern "C" void kernel_launch(void* const* d_in, const int* in_sizes, int n_in,
                              void* d_out, int out_size) {
    const float* x  = (const float*)d_in[0];
    const void*  ei = d_in[1];
    const float* W  = (const float*)d_in[2];
    const float* B  = (const float*)d_in[3];
    float*       out = (float*)d_out;

    int n_nodes = in_sizes[0] / IN_F;
    int E       = in_sizes[1] / 2;

    // 4 co-resident blocks/SM (guaranteed by __launch_bounds__(256,4); tiny smem)
    static int s_nblocks = 0;
    if (s_nblocks == 0) {
        int sm = 0;
        cudaDeviceGetAttribute(&sm, cudaDevAttrMultiProcessorCount, 0);
        if (sm <= 0) sm = 148;
        s_nblocks = sm * 4;
    }

    prep_kernel<<<s_nblocks, PREP_T>>>(ei, (const float4*)B, E, n_nodes, s_nblocks);
    {
        long long threads = (long long)n_nodes * 32;
        int blocks = (int)((threads + 255) / 256);
        gather_kernel<<<blocks, 256>>>(x, n_nodes);
    }
    combine_kernel<<<(n_nodes + TILE_N - 1) / TILE_N, 256>>>(x, W, B, out, n_nodes);
}

// round 14
// speedup vs baseline: 1.1938x; 1.1938x over previous
#include <cuda_runtime.h>

#define IN_F   128
#define OUT_F  128
#define MAX_NODES 10000
#define MAX_EDGES 640000
#define TILE_N 32
#define KK     256     // fused K dimension: [agg_norm | x]
#define KC     32      // K-chunk size for combine

// Scratch (no allocations allowed anywhere). __device__ globals are
// zero-initialized at module load; g_cnt is re-zeroed by gather_kernel each
// call so every invocation sees identical state (deterministic).
__device__ float4 g_agg4[MAX_NODES * (IN_F / 4)];  // normalized aggregate
__device__ int    g_cnt[MAX_NODES];                // in-degree counts (zero at entry)
__device__ int    g_off[MAX_NODES + 1];            // CSR offsets
__device__ unsigned g_rank[MAX_EDGES];             // packed dst<<18 | within-dst rank
__device__ int    g_srcl[MAX_EDGES];               // CSR-ordered src indices
__device__ int    g_kmax;                          // 128 if B==0, else 256

// Per-block edge-index dtype detect: int64 values < 2^32 have zero high words.
__device__ __forceinline__ int detect_is64(const unsigned int* __restrict__ ei_w,
                                           int E, int* s_flag) {
    if (threadIdx.x < 32) {
        unsigned int v = ((int)threadIdx.x < E) ? ei_w[2 * threadIdx.x + 1] : 0u;
        unsigned int any = __ballot_sync(0xffffffffu, v != 0u);
        if (threadIdx.x == 0) *s_flag = (any == 0u) ? 1 : 0;
    }
    __syncthreads();
    return *s_flag;
}

__device__ __forceinline__ int load_idx_d(const void* __restrict__ ei,
                                          long long pos, int is64) {
    if (is64) return (int)((const long long*)ei)[pos];
    return ((const int*)ei)[pos];
}

// ---------------------------------------------------------------------------
// 1) in-degree histogram + rank capture: one edge per thread.
//    Rank word also carries dst (dst<<18 | rank) so fill never re-reads the
//    dst half of edge_index.
// ---------------------------------------------------------------------------
__global__ void deg_kernel(const void* __restrict__ ei, int E, int n_nodes) {
    __shared__ int s_is64;
    int is64 = detect_is64((const unsigned int*)ei, E, &s_is64);
    int e = blockIdx.x * blockDim.x + threadIdx.x;
    if (e < E) {
        int dst = min(max(load_idx_d(ei, (long long)E + e, is64), 0), n_nodes - 1);
        unsigned r = (unsigned)atomicAdd(&g_cnt[dst], 1);
        if (r > 0x3FFFFu) r = 0x3FFFFu;            // degenerate-graph clamp
        g_rank[e] = ((unsigned)dst << 18) | r;
    }
}

// ---------------------------------------------------------------------------
// 2) exclusive scan of counts -> offsets (warp-shuffle, single block).
//    Also detects B == 0 so combine can skip the x@B.T half.
// ---------------------------------------------------------------------------
__global__ __launch_bounds__(1024, 1)
void scan_kernel(const float4* __restrict__ B4, int n_nodes) {
    const int PER = 10;                 // 1024*10 = 10240 >= 10000
    __shared__ int wsum[32];
    int t = threadIdx.x, lane = t & 31, wid = t >> 5;
    int base = t * PER;

    // B == 0 check (64 KB), OR-reduced across the block
    int nz = 0;
#pragma unroll
    for (int i = 0; i < 4; i++) {
        float4 b = B4[t + i * 1024];
        if (b.x != 0.f || b.y != 0.f || b.z != 0.f || b.w != 0.f) nz = 1;
    }
    int bnz = __syncthreads_or(nz);
    if (t == 0) g_kmax = bnz ? KK : IN_F;

    int loc[PER];
    int s = 0;
#pragma unroll
    for (int i = 0; i < PER; i++) {
        int idx = base + i;
        int c = (idx < n_nodes) ? g_cnt[idx] : 0;
        loc[i] = s;
        s += c;
    }
    int v = s;
#pragma unroll
    for (int o = 1; o < 32; o <<= 1) {
        int u = __shfl_up_sync(0xffffffffu, v, o);
        if (lane >= o) v += u;
    }
    if (lane == 31) wsum[wid] = v;
    __syncthreads();
    if (wid == 0) {
        int w = wsum[lane];
#pragma unroll
        for (int o = 1; o < 32; o <<= 1) {
            int u = __shfl_up_sync(0xffffffffu, w, o);
            if (lane >= o) w += u;
        }
        wsum[lane] = w;
    }
    __syncthreads();
    int wbase = (wid == 0) ? 0 : wsum[wid - 1];
    int tbase = wbase + (v - s);
#pragma unroll
    for (int i = 0; i < PER; i++) {
        int idx = base + i;
        if (idx < n_nodes) g_off[idx] = tbase + loc[i];
    }
    if (t == 0) g_off[n_nodes] = wsum[31];
}

// ---------------------------------------------------------------------------
// 3) bucket fill, ATOMIC-FREE: pos = off[dst] + rank, dst+rank from one
//    packed coalesced load; only the src half of edge_index is re-read.
// ---------------------------------------------------------------------------
__global__ void fill_kernel(const void* __restrict__ ei, int E, int n_nodes) {
    __shared__ int s_is64;
    int is64 = detect_is64((const unsigned int*)ei, E, &s_is64);
    int e = blockIdx.x * blockDim.x + threadIdx.x;
    if (e < E) {
        int src = min(max(load_idx_d(ei, e, is64), 0), n_nodes - 1);
        unsigned pk = g_rank[e];
        int dst = (int)(pk >> 18);
        int pos = g_off[dst] + (int)(pk & 0x3FFFFu);
        if (pos < MAX_EDGES) g_srcl[pos] = src;
    }
}

// ---------------------------------------------------------------------------
// 4) gather: one warp per node. 32 lanes x float4 cover the 128-f row.
//    At the measured L2 sustained-throughput ceiling (~328 MB of row reads).
//    Also re-zeroes g_cnt for the next invocation.
// ---------------------------------------------------------------------------
__global__ __launch_bounds__(256)
void gather_kernel(const float* __restrict__ x, int n_nodes) {
    int warp = (int)((blockIdx.x * (long long)blockDim.x + threadIdx.x) >> 5);
    int lane = threadIdx.x & 31;
    if (warp >= n_nodes) return;

    int beg = g_off[warp];
    int end = g_off[warp + 1];
    if (lane == 0) g_cnt[warp] = 0;      // reset for next invocation
    const float4* x4 = (const float4*)x;

    float4 acc = make_float4(0.f, 0.f, 0.f, 0.f);
    int j = beg;
    for (; j + 8 <= end; j += 8) {
        int i0 = g_srcl[j + 0], i1 = g_srcl[j + 1];
        int i2 = g_srcl[j + 2], i3 = g_srcl[j + 3];
        int i4 = g_srcl[j + 4], i5 = g_srcl[j + 5];
        int i6 = g_srcl[j + 6], i7 = g_srcl[j + 7];
        float4 v0 = x4[(size_t)i0 * (IN_F / 4) + lane];
        float4 v1 = x4[(size_t)i1 * (IN_F / 4) + lane];
        float4 v2 = x4[(size_t)i2 * (IN_F / 4) + lane];
        float4 v3 = x4[(size_t)i3 * (IN_F / 4) + lane];
        float4 v4 = x4[(size_t)i4 * (IN_F / 4) + lane];
        float4 v5 = x4[(size_t)i5 * (IN_F / 4) + lane];
        float4 v6 = x4[(size_t)i6 * (IN_F / 4) + lane];
        float4 v7 = x4[(size_t)i7 * (IN_F / 4) + lane];
        acc.x += (v0.x + v1.x) + (v2.x + v3.x) + (v4.x + v5.x) + (v6.x + v7.x);
        acc.y += (v0.y + v1.y) + (v2.y + v3.y) + (v4.y + v5.y) + (v6.y + v7.y);
        acc.z += (v0.z + v1.z) + (v2.z + v3.z) + (v4.z + v5.z) + (v6.z + v7.z);
        acc.w += (v0.w + v1.w) + (v2.w + v3.w) + (v4.w + v5.w) + (v6.w + v7.w);
    }
    for (; j < end; j++) {
        int idx = g_srcl[j];
        float4 v = x4[(size_t)idx * (IN_F / 4) + lane];
        acc.x += v.x; acc.y += v.y; acc.z += v.z; acc.w += v.w;
    }
    int deg = end - beg;
    float inv = 1.0f / (float)((deg == 0) ? 1 : deg);
    acc.x *= inv; acc.y *= inv; acc.z *= inv; acc.w *= inv;
    g_agg4[(size_t)warp * (IN_F / 4) + lane] = acc;
}

// ---------------------------------------------------------------------------
// 5) combine (R9-proven): out = agg_norm @ W^T (+ x @ B.T iff B != 0).
//    Packed f32x2 FMA; A tile transposed so a node pair is one ld.shared.b64.
// ---------------------------------------------------------------------------
__global__ __launch_bounds__(256)
void combine_kernel(const float* __restrict__ x,
                    const float* __restrict__ W,
                    const float* __restrict__ B,
                    float* __restrict__ out, int n_nodes) {
    __shared__ float Wsh[KC][OUT_F + 4];      // [kk][o], row stride 132
    __shared__ float Ash[KC][TILE_N + 2];     // transposed [kk][node], stride 34

    int tid = threadIdx.x;
    int n0 = blockIdx.x * TILE_N;
    const float* agg = (const float*)g_agg4;
    int kmax = g_kmax;                        // uniform: 128 (B==0) or 256

    int og = tid & 31;   // outputs [og*4, og*4+3]
    int ng = tid >> 5;   // nodes   [ng*4, ng*4+3]

    unsigned long long acc[2][4];
#pragma unroll
    for (int p = 0; p < 2; p++)
#pragma unroll
        for (int o = 0; o < 4; o++) acc[p][o] = 0ull;

    for (int kc = 0; kc < kmax; kc += KC) {
        for (int i = tid; i < KC * OUT_F; i += 256) {
            int kk = i & (KC - 1);
            int o  = i >> 5;
            int kg = kc + kk;
            Wsh[kk][o] = (kg < IN_F) ? W[o * IN_F + kg]
                                     : B[o * IN_F + (kg - IN_F)];
        }
        for (int i = tid; i < TILE_N * KC; i += 256) {
            int nl = i >> 5;
            int kk = i & (KC - 1);
            int n  = n0 + nl;
            int kg = kc + kk;
            float v = 0.0f;
            if (n < n_nodes)
                v = (kg < IN_F) ? agg[n * IN_F + kg]
                                : x[n * IN_F + (kg - IN_F)];
            Ash[kk][nl] = v;
        }
        __syncthreads();

#pragma unroll
        for (int kk = 0; kk < KC; kk++) {
            float4 w = *(const float4*)&Wsh[kk][og * 4];
            unsigned long long wx, wy, wz, ww;
            asm("mov.b64 %0, {%1, %1};" : "=l"(wx) : "f"(w.x));
            asm("mov.b64 %0, {%1, %1};" : "=l"(wy) : "f"(w.y));
            asm("mov.b64 %0, {%1, %1};" : "=l"(wz) : "f"(w.z));
            asm("mov.b64 %0, {%1, %1};" : "=l"(ww) : "f"(w.w));
#pragma unroll
            for (int p = 0; p < 2; p++) {
                unsigned long long a2 =
                    *(const unsigned long long*)&Ash[kk][ng * 4 + p * 2];
                asm("fma.rn.f32x2 %0, %1, %2, %0;" : "+l"(acc[p][0]) : "l"(wx), "l"(a2));
                asm("fma.rn.f32x2 %0, %1, %2, %0;" : "+l"(acc[p][1]) : "l"(wy), "l"(a2));
                asm("fma.rn.f32x2 %0, %1, %2, %0;" : "+l"(acc[p][2]) : "l"(wz), "l"(a2));
                asm("fma.rn.f32x2 %0, %1, %2, %0;" : "+l"(acc[p][3]) : "l"(ww), "l"(a2));
            }
        }
        __syncthreads();
    }

#pragma unroll
    for (int p = 0; p < 2; p++) {
        float4 r0, r1;
        asm("mov.b64 {%0, %1}, %2;" : "=f"(r0.x), "=f"(r1.x) : "l"(acc[p][0]));
        asm("mov.b64 {%0, %1}, %2;" : "=f"(r0.y), "=f"(r1.y) : "l"(acc[p][1]));
        asm("mov.b64 {%0, %1}, %2;" : "=f"(r0.z), "=f"(r1.z) : "l"(acc[p][2]));
        asm("mov.b64 {%0, %1}, %2;" : "=f"(r0.w), "=f"(r1.w) : "l"(acc[p][3]));
        int na = n0 + ng * 4 + p * 2;
        int nb = na + 1;
        if (na < n_nodes) *(float4*)(out + (size_t)na * OUT_F + og * 4) = r0;
        if (nb < n_nodes) *(float4*)(out + (size_t)nb * OUT_F + og * 4) = r1;
    }
}

// ---------------------------------------------------------------------------
// kernel_launch
// Inputs: x [10000,128] f32, edge_index [2,640000] (int32 OR int64 — detected
// at runtime), W [128,128] f32, B [128,128] f32. Output: [10000,128] f32.
// ---------------------------------------------------------------------------
extern "C" void kernel_launch(void* const* d_in, const int* in_sizes, int n_in,
                              void* d_out, int out_size) {
    const float* x  = (const float*)d_in[0];
    const void*  ei = d_in[1];
    const float* W  = (const float*)d_in[2];
    const float* B  = (const float*)d_in[3];
    float*       out = (float*)d_out;

    int n_nodes = in_sizes[0] / IN_F;
    int E       = in_sizes[1] / 2;

    deg_kernel<<<(E + 255) / 256, 256>>>(ei, E, n_nodes);
    scan_kernel<<<1, 1024>>>((const float4*)B, n_nodes);
    fill_kernel<<<(E + 255) / 256, 256>>>(ei, E, n_nodes);
    {
        long long threads = (long long)n_nodes * 32;
        int blocks = (int)((threads + 255) / 256);
        gather_kernel<<<blocks, 256>>>(x, n_nodes);
    }
    combine_kernel<<<(n_nodes + TILE_N - 1) / TILE_N, 256>>>(x, W, B, out, n_nodes);
}

// round 15
// speedup vs baseline: 1.2274x; 1.0281x over previous
#include <cuda_runtime.h>

#define IN_F   128
#define OUT_F  128
#define MAX_NODES 10000
#define MAX_EDGES 640000
#define TILE_N 32
#define KK     256     // fused K dimension: [agg_norm | x]
#define KC     32      // K-chunk size for combine

// Scratch (no allocations allowed anywhere). __device__ globals are
// zero-initialized at module load; g_cnt is re-zeroed by gather_kernel each
// call so every invocation sees identical state (deterministic).
__device__ float4 g_agg4[MAX_NODES * (IN_F / 4)];  // normalized aggregate
__device__ int    g_cnt[MAX_NODES];                // in-degree counts (zero at entry)
__device__ int    g_off[MAX_NODES + 1];            // CSR offsets
__device__ unsigned g_rank[MAX_EDGES];             // packed dst<<18 | within-dst rank
__device__ int    g_srcl[MAX_EDGES];               // CSR-ordered src indices
__device__ int    g_kmax;                          // 128 if B==0, else 256

// Per-block edge-index dtype detect: int64 values < 2^32 have zero high words.
__device__ __forceinline__ int detect_is64(const unsigned int* __restrict__ ei_w,
                                           int E, int* s_flag) {
    if (threadIdx.x < 32) {
        unsigned int v = ((int)threadIdx.x < E) ? ei_w[2 * threadIdx.x + 1] : 0u;
        unsigned int any = __ballot_sync(0xffffffffu, v != 0u);
        if (threadIdx.x == 0) *s_flag = (any == 0u) ? 1 : 0;
    }
    __syncthreads();
    return *s_flag;
}

// 32-bit low-word index load: correct for both int32 and little-endian int64
// with values < 2^31. Halves index traffic on the int64 path.
__device__ __forceinline__ int load_idx_lo(const void* __restrict__ ei,
                                           long long pos, int is64) {
    return ((const int*)ei)[is64 ? (pos << 1) : pos];
}

// ---------------------------------------------------------------------------
// 1) in-degree histogram + rank capture: one edge per thread.
//    Rank word carries dst (dst<<18 | rank) so fill never re-reads dst.
// ---------------------------------------------------------------------------
__global__ void deg_kernel(const void* __restrict__ ei, int E, int n_nodes) {
    __shared__ int s_is64;
    int is64 = detect_is64((const unsigned int*)ei, E, &s_is64);
    int e = blockIdx.x * blockDim.x + threadIdx.x;
    if (e < E) {
        int dst = min(max(load_idx_lo(ei, (long long)E + e, is64), 0), n_nodes - 1);
        unsigned r = (unsigned)atomicAdd(&g_cnt[dst], 1);
        if (r > 0x3FFFFu) r = 0x3FFFFu;            // degenerate-graph clamp
        g_rank[e] = ((unsigned)dst << 18) | r;
    }
}

// ---------------------------------------------------------------------------
// 2) exclusive scan of counts -> offsets (warp-shuffle, single block).
//    PDL secondary: B==0 check (input-only) runs BEFORE the grid sync.
// ---------------------------------------------------------------------------
__global__ __launch_bounds__(1024, 1)
void scan_kernel(const float4* __restrict__ B4, int n_nodes) {
    const int PER = 10;                 // 1024*10 = 10240 >= 10000
    __shared__ int wsum[32];
    int t = threadIdx.x, lane = t & 31, wid = t >> 5;
    int base = t * PER;

    // --- preamble (independent of deg): B == 0 check (64 KB) ---
    int nz = 0;
#pragma unroll
    for (int i = 0; i < 4; i++) {
        float4 b = B4[t + i * 1024];
        if (b.x != 0.f || b.y != 0.f || b.z != 0.f || b.w != 0.f) nz = 1;
    }
    int bnz = __syncthreads_or(nz);
    if (t == 0) g_kmax = bnz ? KK : IN_F;

    cudaGridDependencySynchronize();    // wait for deg's counts

    int loc[PER];
    int s = 0;
#pragma unroll
    for (int i = 0; i < PER; i++) {
        int idx = base + i;
        int c = (idx < n_nodes) ? g_cnt[idx] : 0;
        loc[i] = s;
        s += c;
    }
    int v = s;
#pragma unroll
    for (int o = 1; o < 32; o <<= 1) {
        int u = __shfl_up_sync(0xffffffffu, v, o);
        if (lane >= o) v += u;
    }
    if (lane == 31) wsum[wid] = v;
    __syncthreads();
    if (wid == 0) {
        int w = wsum[lane];
#pragma unroll
        for (int o = 1; o < 32; o <<= 1) {
            int u = __shfl_up_sync(0xffffffffu, w, o);
            if (lane >= o) w += u;
        }
        wsum[lane] = w;
    }
    __syncthreads();
    int wbase = (wid == 0) ? 0 : wsum[wid - 1];
    int tbase = wbase + (v - s);
#pragma unroll
    for (int i = 0; i < PER; i++) {
        int idx = base + i;
        if (idx < n_nodes) g_off[idx] = tbase + loc[i];
    }
    if (t == 0) g_off[n_nodes] = wsum[31];
}

// ---------------------------------------------------------------------------
// 3) bucket fill, ATOMIC-FREE. PDL secondary: the src load (input-only)
//    issues before the grid sync; g_rank/g_off reads after.
// ---------------------------------------------------------------------------
__global__ void fill_kernel(const void* __restrict__ ei, int E, int n_nodes) {
    __shared__ int s_is64;
    int is64 = detect_is64((const unsigned int*)ei, E, &s_is64);
    int e = blockIdx.x * blockDim.x + threadIdx.x;
    int src = 0;
    if (e < E) src = min(max(load_idx_lo(ei, e, is64), 0), n_nodes - 1);

    cudaGridDependencySynchronize();    // wait for deg (ranks) + scan (offsets)

    if (e < E) {
        unsigned pk = g_rank[e];
        int dst = (int)(pk >> 18);
        int pos = g_off[dst] + (int)(pk & 0x3FFFFu);
        if (pos < MAX_EDGES) g_srcl[pos] = src;
    }
}

// ---------------------------------------------------------------------------
// 4) gather: one warp per node (HW LTS-cap bound). PDL secondary.
//    Also re-zeroes g_cnt for the next invocation.
// ---------------------------------------------------------------------------
__global__ __launch_bounds__(256)
void gather_kernel(const float* __restrict__ x, int n_nodes) {
    int warp = (int)((blockIdx.x * (long long)blockDim.x + threadIdx.x) >> 5);
    int lane = threadIdx.x & 31;

    cudaGridDependencySynchronize();    // wait for fill's CSR
    if (warp >= n_nodes) return;

    int beg = g_off[warp];
    int end = g_off[warp + 1];
    if (lane == 0) g_cnt[warp] = 0;      // reset for next invocation
    const float4* x4 = (const float4*)x;

    float4 acc = make_float4(0.f, 0.f, 0.f, 0.f);
    int j = beg;
    for (; j + 8 <= end; j += 8) {
        int i0 = g_srcl[j + 0], i1 = g_srcl[j + 1];
        int i2 = g_srcl[j + 2], i3 = g_srcl[j + 3];
        int i4 = g_srcl[j + 4], i5 = g_srcl[j + 5];
        int i6 = g_srcl[j + 6], i7 = g_srcl[j + 7];
        float4 v0 = x4[(size_t)i0 * (IN_F / 4) + lane];
        float4 v1 = x4[(size_t)i1 * (IN_F / 4) + lane];
        float4 v2 = x4[(size_t)i2 * (IN_F / 4) + lane];
        float4 v3 = x4[(size_t)i3 * (IN_F / 4) + lane];
        float4 v4 = x4[(size_t)i4 * (IN_F / 4) + lane];
        float4 v5 = x4[(size_t)i5 * (IN_F / 4) + lane];
        float4 v6 = x4[(size_t)i6 * (IN_F / 4) + lane];
        float4 v7 = x4[(size_t)i7 * (IN_F / 4) + lane];
        acc.x += (v0.x + v1.x) + (v2.x + v3.x) + (v4.x + v5.x) + (v6.x + v7.x);
        acc.y += (v0.y + v1.y) + (v2.y + v3.y) + (v4.y + v5.y) + (v6.y + v7.y);
        acc.z += (v0.z + v1.z) + (v2.z + v3.z) + (v4.z + v5.z) + (v6.z + v7.z);
        acc.w += (v0.w + v1.w) + (v2.w + v3.w) + (v4.w + v5.w) + (v6.w + v7.w);
    }
    for (; j < end; j++) {
        int idx = g_srcl[j];
        float4 v = x4[(size_t)idx * (IN_F / 4) + lane];
        acc.x += v.x; acc.y += v.y; acc.z += v.z; acc.w += v.w;
    }
    int deg = end - beg;
    float inv = 1.0f / (float)((deg == 0) ? 1 : deg);
    acc.x *= inv; acc.y *= inv; acc.z *= inv; acc.w *= inv;
    g_agg4[(size_t)warp * (IN_F / 4) + lane] = acc;
}

// ---------------------------------------------------------------------------
// 5) combine: out = agg_norm @ W^T (+ x @ B.T iff B != 0). PDL secondary:
//    the first W tile (input-only) loads before the grid sync.
// ---------------------------------------------------------------------------
__global__ __launch_bounds__(256)
void combine_kernel(const float* __restrict__ x,
                    const float* __restrict__ W,
                    const float* __restrict__ B,
                    float* __restrict__ out, int n_nodes) {
    __shared__ float Wsh[KC][OUT_F + 4];      // [kk][o], row stride 132
    __shared__ float Ash[KC][TILE_N + 2];     // transposed [kk][node], stride 34

    int tid = threadIdx.x;
    int n0 = blockIdx.x * TILE_N;
    const float* agg = (const float*)g_agg4;

    // --- preamble (input-only): load the kc=0 W tile ---
    for (int i = tid; i < KC * OUT_F; i += 256) {
        int kk = i & (KC - 1);
        int o  = i >> 5;
        Wsh[kk][o] = W[o * IN_F + kk];
    }

    cudaGridDependencySynchronize();          // wait for gather (agg) + scan (kmax)
    int kmax = g_kmax;                        // uniform: 128 (B==0) or 256

    int og = tid & 31;   // outputs [og*4, og*4+3]
    int ng = tid >> 5;   // nodes   [ng*4, ng*4+3]

    unsigned long long acc[2][4];
#pragma unroll
    for (int p = 0; p < 2; p++)
#pragma unroll
        for (int o = 0; o < 4; o++) acc[p][o] = 0ull;

    for (int kc = 0; kc < kmax; kc += KC) {
        if (kc > 0) {
            __syncthreads();                  // drain previous chunk's readers
            for (int i = tid; i < KC * OUT_F; i += 256) {
                int kk = i & (KC - 1);
                int o  = i >> 5;
                int kg = kc + kk;
                Wsh[kk][o] = (kg < IN_F) ? W[o * IN_F + kg]
                                         : B[o * IN_F + (kg - IN_F)];
            }
        }
        for (int i = tid; i < TILE_N * KC; i += 256) {
            int nl = i >> 5;
            int kk = i & (KC - 1);
            int n  = n0 + nl;
            int kg = kc + kk;
            float v = 0.0f;
            if (n < n_nodes)
                v = (kg < IN_F) ? agg[n * IN_F + kg]
                                : x[n * IN_F + (kg - IN_F)];
            Ash[kk][nl] = v;
        }
        __syncthreads();

#pragma unroll
        for (int kk = 0; kk < KC; kk++) {
            float4 w = *(const float4*)&Wsh[kk][og * 4];
            unsigned long long wx, wy, wz, ww;
            asm("mov.b64 %0, {%1, %1};" : "=l"(wx) : "f"(w.x));
            asm("mov.b64 %0, {%1, %1};" : "=l"(wy) : "f"(w.y));
            asm("mov.b64 %0, {%1, %1};" : "=l"(wz) : "f"(w.z));
            asm("mov.b64 %0, {%1, %1};" : "=l"(ww) : "f"(w.w));
#pragma unroll
            for (int p = 0; p < 2; p++) {
                unsigned long long a2 =
                    *(const unsigned long long*)&Ash[kk][ng * 4 + p * 2];
                asm("fma.rn.f32x2 %0, %1, %2, %0;" : "+l"(acc[p][0]) : "l"(wx), "l"(a2));
                asm("fma.rn.f32x2 %0, %1, %2, %0;" : "+l"(acc[p][1]) : "l"(wy), "l"(a2));
                asm("fma.rn.f32x2 %0, %1, %2, %0;" : "+l"(acc[p][2]) : "l"(wz), "l"(a2));
                asm("fma.rn.f32x2 %0, %1, %2, %0;" : "+l"(acc[p][3]) : "l"(ww), "l"(a2));
            }
        }
    }

#pragma unroll
    for (int p = 0; p < 2; p++) {
        float4 r0, r1;
        asm("mov.b64 {%0, %1}, %2;" : "=f"(r0.x), "=f"(r1.x) : "l"(acc[p][0]));
        asm("mov.b64 {%0, %1}, %2;" : "=f"(r0.y), "=f"(r1.y) : "l"(acc[p][1]));
        asm("mov.b64 {%0, %1}, %2;" : "=f"(r0.z), "=f"(r1.z) : "l"(acc[p][2]));
        asm("mov.b64 {%0, %1}, %2;" : "=f"(r0.w), "=f"(r1.w) : "l"(acc[p][3]));
        int na = n0 + ng * 4 + p * 2;
        int nb = na + 1;
        if (na < n_nodes) *(float4*)(out + (size_t)na * OUT_F + og * 4) = r0;
        if (nb < n_nodes) *(float4*)(out + (size_t)nb * OUT_F + og * 4) = r1;
    }
}

// ---------------------------------------------------------------------------
// kernel_launch — secondaries use programmatic stream serialization (PDL) so
// each launch overlaps its predecessor's drain; ordering enforced by the
// cudaGridDependencySynchronize() calls above.
// ---------------------------------------------------------------------------
template <typename... Args>
static inline void launch_pdl(void (*kern)(Args...), dim3 grid, dim3 block,
                              Args... args) {
    cudaLaunchConfig_t cfg = {};
    cfg.gridDim = grid;
    cfg.blockDim = block;
    cudaLaunchAttribute attr[1];
    attr[0].id = cudaLaunchAttributeProgrammaticStreamSerialization;
    attr[0].val.programmaticStreamSerializationAllowed = 1;
    cfg.attrs = attr;
    cfg.numAttrs = 1;
    cudaLaunchKernelEx(&cfg, kern, args...);
}

extern "C" void kernel_launch(void* const* d_in, const int* in_sizes, int n_in,
                              void* d_out, int out_size) {
    const float* x  = (const float*)d_in[0];
    const void*  ei = d_in[1];
    const float* W  = (const float*)d_in[2];
    const float* B  = (const float*)d_in[3];
    float*       out = (float*)d_out;

    int n_nodes = in_sizes[0] / IN_F;
    int E       = in_sizes[1] / 2;

    deg_kernel<<<(E + 255) / 256, 256>>>(ei, E, n_nodes);
    launch_pdl(scan_kernel, dim3(1), dim3(1024), (const float4*)B, n_nodes);
    launch_pdl(fill_kernel, dim3((E + 255) / 256), dim3(256), ei, E, n_nodes);
    {
        long long threads = (long long)n_nodes * 32;
        int blocks = (int)((threads + 255) / 256);
        launch_pdl(gather_kernel, dim3(blocks), dim3(256), x, n_nodes);
    }
    launch_pdl(combine_kernel, dim3((n_nodes + TILE_N - 1) / TILE_N), dim3(256),
               x, W, B, out, n_nodes);
}